// round 10
// baseline (speedup 1.0000x reference)
#include <cuda_runtime.h>
#include <cuda_bf16.h>
#include <math.h>
#include <stdint.h>

#define D 128
#define NMAX 100000
#define EMAX 500000

// -------- device scratch (allocation-free: __device__ globals) --------
__device__ float g_pA[(size_t)NMAX * D];   // softmax(logits_A)
__device__ float g_pB[(size_t)NMAX * D];   // softmax(logits_B)
// CSR per edge type: 0=AB(dst in B, src p_A) 1=BA(dst in A, src p_B) 2=AA(dst in A, src p_A)
__device__ int g_off[3][NMAX + 1];         // counts then offsets (off[i] = row start)
__device__ int g_cur[3][NMAX + 1];         // fill cursors
__device__ int g_srcs[3][EMAX];            // src ids grouped by dst
// W^T (softplus-transformed), hi/lo bf16 split, plain [n][k] row-major.
// 0:AB_hi 1:AB_lo 2:BA_hi 3:BA_lo 4:AA_hi 5:AA_lo
__device__ __nv_bfloat16 g_Wt[6 * 128 * 128];

// -------- helpers --------
__device__ __forceinline__ float softplusf(float x) {
    return fmaxf(x, 0.0f) + log1pf(__expf(-fabsf(x)));
}
__device__ __forceinline__ uint32_t s2u(const void* p) {
    uint32_t a;
    asm("{ .reg .u64 t; cvta.to.shared.u64 t, %1; cvt.u32.u64 %0, t; }"
        : "=r"(a) : "l"(p));
    return a;
}
__device__ __forceinline__ void ldsm_x4(uint32_t& r0, uint32_t& r1, uint32_t& r2,
                                        uint32_t& r3, uint32_t a) {
    asm volatile("ldmatrix.sync.aligned.m8n8.x4.shared.b16 {%0,%1,%2,%3}, [%4];"
                 : "=r"(r0), "=r"(r1), "=r"(r2), "=r"(r3) : "r"(a));
}
__device__ __forceinline__ void ldsm_x2(uint32_t& r0, uint32_t& r1, uint32_t a) {
    asm volatile("ldmatrix.sync.aligned.m8n8.x2.shared.b16 {%0,%1}, [%2];"
                 : "=r"(r0), "=r"(r1) : "r"(a));
}
__device__ __forceinline__ void mma16816(float* c, const uint32_t* A, const uint32_t* B) {
    asm volatile(
        "mma.sync.aligned.m16n8k16.row.col.f32.bf16.bf16.f32 "
        "{%0,%1,%2,%3}, {%4,%5,%6,%7}, {%8,%9}, {%0,%1,%2,%3};"
        : "+f"(c[0]), "+f"(c[1]), "+f"(c[2]), "+f"(c[3])
        : "r"(A[0]), "r"(A[1]), "r"(A[2]), "r"(A[3]), "r"(B[0]), "r"(B[1]));
}

// -------- kernel 1: fused softmax (one warp per row) --------
__global__ void softmax_kernel(const float* __restrict__ A,
                               const float* __restrict__ B,
                               int nA, int nTot) {
    int gw   = (blockIdx.x * blockDim.x + threadIdx.x) >> 5;
    int lane = threadIdx.x & 31;
    if (gw >= nTot) return;
    const float* src;
    float* dst;
    if (gw < nA) { src = A + (size_t)gw * D;        dst = g_pA + (size_t)gw * D; }
    else         { src = B + (size_t)(gw - nA) * D; dst = g_pB + (size_t)(gw - nA) * D; }
    float4 v = ((const float4*)src)[lane];
    float m = fmaxf(fmaxf(v.x, v.y), fmaxf(v.z, v.w));
    #pragma unroll
    for (int o = 16; o; o >>= 1) m = fmaxf(m, __shfl_xor_sync(0xffffffffu, m, o));
    float4 e;
    e.x = __expf(v.x - m); e.y = __expf(v.y - m);
    e.z = __expf(v.z - m); e.w = __expf(v.w - m);
    float s = e.x + e.y + e.z + e.w;
    #pragma unroll
    for (int o = 16; o; o >>= 1) s += __shfl_xor_sync(0xffffffffu, s, o);
    float inv = __frcp_rn(s);
    e.x *= inv; e.y *= inv; e.z *= inv; e.w *= inv;
    ((float4*)dst)[lane] = e;
}

// -------- CSR build --------
__global__ void zero_off_kernel() {
    int i = blockIdx.x * blockDim.x + threadIdx.x;
    int n = 3 * (NMAX + 1);
    if (i < n) ((int*)g_off)[i] = 0;
}

__device__ __forceinline__ bool resolve_edge(int gw, const int* eAB, const int* eBA,
                                             const int* eAA, int EAB, int EBA, int EAA,
                                             int& t, const int*& e, int& E, int& i) {
    if (gw < EAB)               { t = 0; e = eAB; E = EAB; i = gw; return true; }
    if ((gw -= EAB) < EBA)      { t = 1; e = eBA; E = EBA; i = gw; return true; }
    if ((gw -= EBA) < EAA)      { t = 2; e = eAA; E = EAA; i = gw; return true; }
    return false;
}

__global__ void count_kernel(const int* __restrict__ eAB, const int* __restrict__ eBA,
                             const int* __restrict__ eAA, int EAB, int EBA, int EAA) {
    int gw = blockIdx.x * blockDim.x + threadIdx.x;
    int t, E, i; const int* e;
    if (!resolve_edge(gw, eAB, eBA, eAA, EAB, EBA, EAA, t, e, E, i)) return;
    atomicAdd(&g_off[t][e[E + i] + 1], 1);
}

// 3 blocks (one per type), 1024 threads: inclusive scan over NMAX+1 elements.
__global__ void scan_kernel() {
    int t = blockIdx.x;
    int* a   = g_off[t];
    int* cur = g_cur[t];
    __shared__ int wsum[32];
    __shared__ int s_carry;
    if (threadIdx.x == 0) s_carry = 0;
    __syncthreads();
    int lane = threadIdx.x & 31, w = threadIdx.x >> 5;
    const int n = NMAX + 1;
    for (int b = 0; b < n; b += 1024) {
        int i = b + threadIdx.x;
        int x = (i < n) ? a[i] : 0;
        int v = x;
        #pragma unroll
        for (int o = 1; o < 32; o <<= 1) {
            int y = __shfl_up_sync(0xffffffffu, v, o);
            if (lane >= o) v += y;
        }
        if (lane == 31) wsum[w] = v;
        __syncthreads();
        if (w == 0) {
            int s = wsum[lane];
            #pragma unroll
            for (int o = 1; o < 32; o <<= 1) {
                int y = __shfl_up_sync(0xffffffffu, s, o);
                if (lane >= o) s += y;
            }
            wsum[lane] = s;
        }
        __syncthreads();
        int carry = s_carry;
        int incl = v + (w > 0 ? wsum[w - 1] : 0) + carry;
        if (i < n) { a[i] = incl; cur[i] = incl; }
        int btot = wsum[31];
        __syncthreads();
        if (threadIdx.x == 0) s_carry = carry + btot;
        __syncthreads();
    }
}

__global__ void fill_kernel(const int* __restrict__ eAB, const int* __restrict__ eBA,
                            const int* __restrict__ eAA, int EAB, int EBA, int EAA) {
    int gw = blockIdx.x * blockDim.x + threadIdx.x;
    int t, E, i; const int* e;
    if (!resolve_edge(gw, eAB, eBA, eAA, EAB, EBA, EAA, t, e, E, i)) return;
    int src = e[i];
    int dst = e[E + i];
    int pos = atomicAdd(&g_cur[t][dst], 1);
    g_srcs[t][pos] = src;
}

// -------- W prep — transpose + softplus + hi/lo split --------
__global__ void prep_w_kernel(const float* __restrict__ Wp0, const float* __restrict__ Wn0,
                              const float* __restrict__ Wp1, const float* __restrict__ Wn1,
                              const float* __restrict__ Wp2, const float* __restrict__ Wn2) {
    int w = blockIdx.x;
    const float* Wp = (w == 0) ? Wp0 : (w == 1) ? Wp1 : Wp2;
    const float* Wn = (w == 0) ? Wn0 : (w == 1) ? Wn1 : Wn2;
    __nv_bfloat16* hi = g_Wt + (size_t)(2 * w) * D * D;
    __nv_bfloat16* lo = g_Wt + (size_t)(2 * w + 1) * D * D;
    for (int idx = threadIdx.x; idx < D * D; idx += blockDim.x) {
        int n = idx & 127;
        int k = idx >> 7;
        float x = Wp[k * D + n] - softplusf(Wn[k * D + n]);
        __nv_bfloat16 h = __float2bfloat16(x);
        __nv_bfloat16 l = __float2bfloat16(x - __bfloat162float(h));
        hi[n * D + k] = h;
        lo[n * D + k] = l;
    }
}

// -------- fused gather + mma.sync bf16x3 GEMM --------
__device__ __forceinline__ const float* sel_P(int t) {
    return (t == 1) ? g_pB : g_pA;
}

// SMEM layout: padded rows, stride 272B (conflict-free LDSM)
#define RSTRIDE 272
#define SM_AHI 0
#define SM_ALO (SM_AHI + 128 * RSTRIDE)
#define SM_BHI (SM_ALO + 128 * RSTRIDE)
#define SM_BLO (SM_BHI + 128 * RSTRIDE)
#define SM_TOT (SM_BLO + 128 * RSTRIDE)

// Warp gathers 16 rows (4 groups of 4 interleaved), fp32 accumulate, hi/lo bf16 to smem.
__device__ __forceinline__ void gather_convert_A(const float* __restrict__ P,
                                                 const int* __restrict__ off,
                                                 const int* __restrict__ srcs,
                                                 int base, int M,
                                                 char* Ahi, char* Alo,
                                                 int wid, int lane) {
    #pragma unroll 1
    for (int g = 0; g < 4; ++g) {
        int r0 = (wid << 4) + (g << 2);
        float4 acc[4];
        int epos[4], eend[4], nsrc[4];
        #pragma unroll
        for (int q = 0; q < 4; ++q) {
            acc[q] = make_float4(0.f, 0.f, 0.f, 0.f);
            int gr = base + r0 + q;
            if (gr < M) { epos[q] = off[gr]; eend[q] = off[gr + 1]; }
            else        { epos[q] = 0;       eend[q] = 0; }
            nsrc[q] = (epos[q] < eend[q]) ? srcs[epos[q]] : 0;
        }
        for (;;) {
            bool h0 = epos[0] < eend[0], h1 = epos[1] < eend[1];
            bool h2 = epos[2] < eend[2], h3 = epos[3] < eend[3];
            if (!(h0 | h1 | h2 | h3)) break;
            float4 v0, v1, v2, v3;
            if (h0) v0 = ((const float4*)(P + (size_t)nsrc[0] * D))[lane];
            if (h1) v1 = ((const float4*)(P + (size_t)nsrc[1] * D))[lane];
            if (h2) v2 = ((const float4*)(P + (size_t)nsrc[2] * D))[lane];
            if (h3) v3 = ((const float4*)(P + (size_t)nsrc[3] * D))[lane];
            // advance + prefetch next src indices (breaks addr dependence)
            if (h0) { if (++epos[0] < eend[0]) nsrc[0] = srcs[epos[0]]; }
            if (h1) { if (++epos[1] < eend[1]) nsrc[1] = srcs[epos[1]]; }
            if (h2) { if (++epos[2] < eend[2]) nsrc[2] = srcs[epos[2]]; }
            if (h3) { if (++epos[3] < eend[3]) nsrc[3] = srcs[epos[3]]; }
            if (h0) { acc[0].x += v0.x; acc[0].y += v0.y; acc[0].z += v0.z; acc[0].w += v0.w; }
            if (h1) { acc[1].x += v1.x; acc[1].y += v1.y; acc[1].z += v1.z; acc[1].w += v1.w; }
            if (h2) { acc[2].x += v2.x; acc[2].y += v2.y; acc[2].z += v2.z; acc[2].w += v2.w; }
            if (h3) { acc[3].x += v3.x; acc[3].y += v3.y; acc[3].z += v3.z; acc[3].w += v3.w; }
        }
        #pragma unroll
        for (int q = 0; q < 4; ++q) {
            float4 v = acc[q];
            __nv_bfloat16 h0 = __float2bfloat16(v.x), h1 = __float2bfloat16(v.y);
            __nv_bfloat16 h2 = __float2bfloat16(v.z), h3 = __float2bfloat16(v.w);
            __nv_bfloat162 hA; hA.x = h0; hA.y = h1;
            __nv_bfloat162 hB; hB.x = h2; hB.y = h3;
            __nv_bfloat162 lA, lB;
            lA.x = __float2bfloat16(v.x - __bfloat162float(h0));
            lA.y = __float2bfloat16(v.y - __bfloat162float(h1));
            lB.x = __float2bfloat16(v.z - __bfloat162float(h2));
            lB.y = __float2bfloat16(v.w - __bfloat162float(h3));
            char* ph = Ahi + (r0 + q) * RSTRIDE + lane * 8;
            char* pl = Alo + (r0 + q) * RSTRIDE + lane * 8;
            *(__nv_bfloat162*)ph = hA; *(__nv_bfloat162*)(ph + 4) = hB;
            *(__nv_bfloat162*)pl = lA; *(__nv_bfloat162*)(pl + 4) = lB;
        }
    }
}

template<int NPAIRS>
__global__ void __launch_bounds__(256, 1)
gemm_mma(int t0, int t1, int wbuf0, int wbuf1, float* __restrict__ out, int M) {
    extern __shared__ char sm[];
    uint32_t sb = s2u(sm);
    int tid = threadIdx.x, w = tid >> 5, lane = tid & 31;
    int mw = (w & 3) << 5;
    int nw = (w >> 2) << 6;
    int base = blockIdx.x << 7;

    float acc[2][8][4];
    #pragma unroll
    for (int a = 0; a < 2; ++a)
        #pragma unroll
        for (int b = 0; b < 8; ++b)
            #pragma unroll
            for (int c = 0; c < 4; ++c) acc[a][b][c] = 0.f;

    int a_row = (lane & 7) + ((lane >> 3) & 1) * 8;
    int a_koff = (lane >> 4) * 8;
    int b_row = lane & 7;
    int b_koff = ((lane >> 3) & 1) * 8;

    #pragma unroll
    for (int p = 0; p < NPAIRS; ++p) {
        if (p > 0) __syncthreads();
        int t = (p == 0) ? t0 : t1;

        // copy W pair (hi/lo) into padded smem
        {
            const float4* gh = (const float4*)(g_Wt + (size_t)(p == 0 ? wbuf0 : wbuf1) * D * D);
            const float4* gl = gh + (D * D / 8);
            for (int i = tid; i < 128 * 16; i += 256) {
                int r = i >> 4, c = i & 15;
                *(float4*)(sm + SM_BHI + r * RSTRIDE + c * 16) = gh[r * 16 + c];
                *(float4*)(sm + SM_BLO + r * RSTRIDE + c * 16) = gl[r * 16 + c];
            }
        }
        // fused CSR gather + convert into A smem
        gather_convert_A(sel_P(t), g_off[t], g_srcs[t], base, M,
                         sm + SM_AHI, sm + SM_ALO, w, lane);
        __syncthreads();

        #pragma unroll
        for (int ks = 0; ks < 8; ++ks) {
            int k0 = ks << 4;
            uint32_t Ahi[2][4], Alo[2][4], Bhi[8][2], Blo[8][2];
            #pragma unroll
            for (int m2 = 0; m2 < 2; ++m2) {
                uint32_t ao = (uint32_t)((mw + (m2 << 4) + a_row) * RSTRIDE
                                          + (k0 + a_koff) * 2);
                ldsm_x4(Ahi[m2][0], Ahi[m2][1], Ahi[m2][2], Ahi[m2][3], sb + SM_AHI + ao);
                ldsm_x4(Alo[m2][0], Alo[m2][1], Alo[m2][2], Alo[m2][3], sb + SM_ALO + ao);
            }
            #pragma unroll
            for (int j = 0; j < 8; ++j) {
                uint32_t bo = (uint32_t)((nw + (j << 3) + b_row) * RSTRIDE
                                          + (k0 + b_koff) * 2);
                ldsm_x2(Bhi[j][0], Bhi[j][1], sb + SM_BHI + bo);
                ldsm_x2(Blo[j][0], Blo[j][1], sb + SM_BLO + bo);
            }
            #pragma unroll
            for (int m2 = 0; m2 < 2; ++m2)
                #pragma unroll
                for (int j = 0; j < 8; ++j) {
                    mma16816(acc[m2][j], Ahi[m2], Bhi[j]);
                    mma16816(acc[m2][j], Ahi[m2], Blo[j]);
                    mma16816(acc[m2][j], Alo[m2], Bhi[j]);
                }
        }
    }

    // epilogue
    int gid = lane >> 2, tig = lane & 3;
    #pragma unroll
    for (int m2 = 0; m2 < 2; ++m2) {
        int r0 = base + mw + (m2 << 4) + gid;
        #pragma unroll
        for (int j = 0; j < 8; ++j) {
            int col = nw + (j << 3) + (tig << 1);
            if (r0 < M)
                *(float2*)(out + (size_t)r0 * D + col) = make_float2(acc[m2][j][0], acc[m2][j][1]);
            if (r0 + 8 < M)
                *(float2*)(out + (size_t)(r0 + 8) * D + col) = make_float2(acc[m2][j][2], acc[m2][j][3]);
        }
    }
}

// -------- launch --------
extern "C" void kernel_launch(void* const* d_in, const int* in_sizes, int n_in,
                              void* d_out, int out_size) {
    const float* logits_A = (const float*)d_in[0];
    const float* logits_B = (const float*)d_in[1];
    const int* eAB = (const int*)d_in[4];
    const int* eBA = (const int*)d_in[5];
    const int* eAA = (const int*)d_in[6];
    const float* WpAB = (const float*)d_in[7];
    const float* WnAB = (const float*)d_in[8];
    const float* WpBA = (const float*)d_in[9];
    const float* WnBA = (const float*)d_in[10];
    const float* WpAA = (const float*)d_in[11];
    const float* WnAA = (const float*)d_in[12];

    int nA = in_sizes[0] / D;
    int nB = in_sizes[1] / D;
    int EAB = in_sizes[4] / 2;
    int EBA = in_sizes[5] / 2;
    int EAA = in_sizes[6] / 2;
    int Etot = EAB + EBA + EAA;

    float* outA = (float*)d_out;
    float* outB = outA + (size_t)nA * D;

    // 1) softmax
    int rows = nA + nB;
    softmax_kernel<<<(rows + 7) / 8, 256>>>(logits_A, logits_B, nA, rows);

    // 2) CSR build
    zero_off_kernel<<<(3 * (NMAX + 1) + 255) / 256, 256>>>();
    count_kernel<<<(Etot + 255) / 256, 256>>>(eAB, eBA, eAA, EAB, EBA, EAA);
    scan_kernel<<<3, 1024>>>();
    fill_kernel<<<(Etot + 255) / 256, 256>>>(eAB, eBA, eAA, EAB, EBA, EAA);

    // 3) W prep
    prep_w_kernel<<<3, 256>>>(WpAB, WnAB, WpBA, WnBA, WpAA, WnAA);

    // 4) fused gather + GEMM
    cudaFuncSetAttribute(gemm_mma<1>, cudaFuncAttributeMaxDynamicSharedMemorySize, SM_TOT);
    cudaFuncSetAttribute(gemm_mma<2>, cudaFuncAttributeMaxDynamicSharedMemorySize, SM_TOT);

    int tilesB = (nB + 127) / 128;
    int tilesA = (nA + 127) / 128;
    // delta_B = gather_AB(p_A) @ W_AB
    gemm_mma<1><<<tilesB, 256, SM_TOT>>>(0, 0, 0, 0, outB, nB);
    // delta_A = gather_BA(p_B) @ W_BA + gather_AA(p_A) @ W_AA
    gemm_mma<2><<<tilesA, 256, SM_TOT>>>(1, 2, 2, 4, outA, nA);
}